// round 15
// baseline (speedup 1.0000x reference)
#include <cuda_runtime.h>
#include <cuda_bf16.h>
#include <cuda_fp16.h>
#include <math.h>
#include <stdint.h>

#define Bc   4
#define Nc   8192
#define Gc   512
#define K1   1536
#define K2   512
#define Mtot (Bc * Nc)   // 32768
#define Mg   (Bc * Gc)   // 2048

// ---------------- scratch ----------------------------------------------------
__device__ unsigned short g_Fh[(size_t)Mg * K1];     // fused features hi (bf16)
__device__ unsigned short g_Fl[(size_t)Mg * K1];     // fused features lo
__device__ unsigned short g_P [(size_t)Mg * 512];    // F @ W1^T (fp16)
__device__ unsigned short g_h1 [(size_t)Mtot * K2];  // hidden (fp16, single)
__device__ unsigned short g_w1h[512 * K1], g_w1l[512 * K1];   // bf16 split
__device__ unsigned short g_w2 [512 * K2];                     // fp16 single
__device__ int   g_idx[Mtot * 3];
__device__ float g_wts[Mtot * 3];
__device__ float g_s1[512], g_t1[512], g_s2[512], g_t2[512];

// ---------------- helpers ----------------------------------------------------
__device__ __forceinline__ uint32_t smem_u32(const void* p) {
    uint32_t a;
    asm("{ .reg .u64 t; cvta.to.shared.u64 t, %1; cvt.u32.u64 %0, t; }" : "=r"(a) : "l"(p));
    return a;
}
__device__ __forceinline__ void cp_async16(uint32_t dst, const void* src) {
    asm volatile("cp.async.cg.shared.global [%0], [%1], 16;" :: "r"(dst), "l"(src));
}
#define CP_COMMIT() asm volatile("cp.async.commit_group;" ::: "memory")
#define CP_WAIT(n)  asm volatile("cp.async.wait_group %0;" :: "n"(n) : "memory")

__device__ __forceinline__ void ldm_x4(uint32_t* r, uint32_t a) {
    asm volatile("ldmatrix.sync.aligned.m8n8.x4.shared.b16 {%0,%1,%2,%3}, [%4];"
                 : "=r"(r[0]), "=r"(r[1]), "=r"(r[2]), "=r"(r[3]) : "r"(a));
}
__device__ __forceinline__ void mma_bf16(float* c, const uint32_t* a, const uint32_t* b) {
    asm volatile("mma.sync.aligned.m16n8k16.row.col.f32.bf16.bf16.f32 "
                 "{%0,%1,%2,%3}, {%4,%5,%6,%7}, {%8,%9}, {%0,%1,%2,%3};"
                 : "+f"(c[0]), "+f"(c[1]), "+f"(c[2]), "+f"(c[3])
                 : "r"(a[0]), "r"(a[1]), "r"(a[2]), "r"(a[3]), "r"(b[0]), "r"(b[1]));
}
__device__ __forceinline__ void mma_fp16(float* c, const uint32_t* a, const uint32_t* b) {
    asm volatile("mma.sync.aligned.m16n8k16.row.col.f32.f16.f16.f32 "
                 "{%0,%1,%2,%3}, {%4,%5,%6,%7}, {%8,%9}, {%0,%1,%2,%3};"
                 : "+f"(c[0]), "+f"(c[1]), "+f"(c[2]), "+f"(c[3])
                 : "r"(a[0]), "r"(a[1]), "r"(a[2]), "r"(a[3]), "r"(b[0]), "r"(b[1]));
}
__device__ __forceinline__ uint32_t swz(uint32_t o) { return o ^ ((o >> 3) & 0x70); }
__device__ __forceinline__ unsigned short bfhi(float v) {
    __nv_bfloat16 h = __float2bfloat16(v);
    return *(unsigned short*)&h;
}
__device__ __forceinline__ unsigned short bflo(float v, unsigned short hb) {
    __nv_bfloat16 h; *(unsigned short*)&h = hb;
    __nv_bfloat16 l = __float2bfloat16(v - __bfloat162float(h));
    return *(unsigned short*)&l;
}
__device__ __forceinline__ unsigned short fphi(float v) {
    __half h = __float2half_rn(v);
    return *(unsigned short*)&h;
}
__device__ __forceinline__ float fp2f(unsigned short u) {
    __half h; *(unsigned short*)&h = u;
    return __half2float(h);
}

// ---------------------------------------------------------------------------
// Union preprocess kernel (validated R11/R14)
// ---------------------------------------------------------------------------
#define PREP_BLKS  2
#define CONVW_BASE 2
#define CONVW_BLKS 3072
#define CONVF_BASE (CONVW_BASE + CONVW_BLKS)    // 3074
#define CONVF_BLKS 3072
#define PRE_BLKS   (CONVF_BASE + CONVF_BLKS)    // 6146

__global__ void __launch_bounds__(256) preproc_kernel(
    const float4* __restrict__ H4, const float4* __restrict__ H8,
    const float4* __restrict__ H12,
    const float* __restrict__ w1, const float* __restrict__ w2,
    const float* __restrict__ b1, const float* __restrict__ g1,
    const float* __restrict__ be1, const float* __restrict__ m1,
    const float* __restrict__ v1,
    const float* __restrict__ b2, const float* __restrict__ g2,
    const float* __restrict__ be2, const float* __restrict__ m2,
    const float* __restrict__ v2)
{
    const int blk = blockIdx.x, tid = threadIdx.x;
    if (blk < PREP_BLKS) {
        int i = blk * 256 + tid;
        if (i < 512) {
            float s = g1[i] * rsqrtf(v1[i] + 1e-5f);
            g_s1[i] = s;
            g_t1[i] = (b1[i] - m1[i]) * s + be1[i];
            float s2 = g2[i] * rsqrtf(v2[i] + 1e-5f);
            g_s2[i] = s2;
            g_t2[i] = (b2[i] - m2[i]) * s2 + be2[i];
        }
    } else if (blk < CONVF_BASE) {
        int i = (blk - CONVW_BASE) * 256 + tid;
        if (i < 512 * K1) {
            float v = w1[i];
            unsigned short h = bfhi(v);
            g_w1h[i] = h;
            g_w1l[i] = bflo(v, h);
        }
        if (i < 512 * K2) {
            g_w2[i] = fphi(w2[i]);
        }
    } else {
        int gid = (blk - CONVF_BASE) * 256 + tid;    // < Mg*384
        if (gid < Mg * 384) {
            int row = gid / 384;
            int c4  = gid - row * 384;
            int seg = c4 >> 7;
            int off = c4 & 127;
            const float4* H = (seg == 0) ? H4 : ((seg == 1) ? H8 : H12);
            float4 v = H[(size_t)row * 128 + off];
            float o[4] = {v.x, v.y, v.z, v.w};
            union { unsigned short u[4]; uint2 q; } Hq, Lq;
#pragma unroll
            for (int j = 0; j < 4; j++) {
                Hq.u[j] = bfhi(o[j]);
                Lq.u[j] = bflo(o[j], Hq.u[j]);
            }
            *reinterpret_cast<uint2*>(g_Fh + (size_t)gid * 4) = Hq.q;
            *reinterpret_cast<uint2*>(g_Fl + (size_t)gid * 4) = Lq.q;
        }
    }
}

// ---------------------------------------------------------------------------
// GEMM configs. BM=64, 2m x 4n warps, 2 CTAs/SM.
// LAYER1 (bf16 3-term, BK=64): stage = 2*ATSZ1 + 2*BTSZ1 = 48 KB
// LAYER2 (fp16 1-term, BK=128): stage = ATSZ2 + BTSZ2 = 48 KB
// ---------------------------------------------------------------------------
static constexpr int BM    = 64;
static constexpr int ATSZ1 = BM * 128;          // 8 KB
static constexpr int BTSZ1 = 128 * 128;         // 16 KB
static constexpr int STG1  = 2 * ATSZ1 + 2 * BTSZ1;   // 48 KB
static constexpr int SMEM1 = 2 * STG1 + 1024;

static constexpr int ATSZ2 = BM * 256;          // 16 KB  (BK=128 fp16)
static constexpr int BTSZ2 = 128 * 256;         // 32 KB
static constexpr int STG2  = ATSZ2 + BTSZ2;     // 48 KB
static constexpr int SMEM2 = 2 * STG2 + 1024;

// ---- LAYER 1 body: P = F @ W1^T, bf16 3-term split -> fp16 P ----
__device__ __forceinline__ void gemm1_body(int bx, int by, char* dsm) {
    uint32_t sb = (smem_u32(dsm) + 1023) & ~1023u;
    const int tid = threadIdx.x, lane = tid & 31, wid = tid >> 5;
    const int wm = wid >> 2, wn = wid & 3;
    const int n0 = bx * 128;
    const int m0 = by * BM;

    auto load_chunk = [&](int kc, int buf) {
        int k0 = kc * 64;
        uint32_t base = sb + buf * STG1;
#pragma unroll
        for (int i = tid; i < BM * 8; i += 256) {
            int r = i >> 3, c = i & 7;
            size_t go = (size_t)(m0 + r) * K1 + k0 + c * 8;
            uint32_t off = swz((uint32_t)(r * 128 + c * 16));
            cp_async16(base + off, g_Fh + go);
            cp_async16(base + ATSZ1 + off, g_Fl + go);
        }
#pragma unroll
        for (int i = tid; i < 128 * 8; i += 256) {
            int r = i >> 3, c = i & 7;
            size_t go = (size_t)(n0 + r) * K1 + k0 + c * 8;
            uint32_t off = swz((uint32_t)(r * 128 + c * 16));
            cp_async16(base + 2 * ATSZ1 + off, g_w1h + go);
            cp_async16(base + 2 * ATSZ1 + BTSZ1 + off, g_w1l + go);
        }
    };

    const int g8 = lane >> 3, i8 = lane & 7;
    uint32_t patA[2], patB[2];
#pragma unroll
    for (int am = 0; am < 2; am++) {
        int r = wm * 32 + am * 16 + (g8 & 1) * 8 + i8;
        patA[am] = swz((uint32_t)(r * 128 + (g8 >> 1) * 16));
    }
#pragma unroll
    for (int j = 0; j < 2; j++) {
        int r = wn * 32 + j * 16 + (g8 >> 1) * 8 + i8;
        patB[j] = swz((uint32_t)(r * 128 + (g8 & 1) * 16));
    }

    float acc[2][4][4];
#pragma unroll
    for (int a = 0; a < 2; a++)
#pragma unroll
        for (int b = 0; b < 4; b++)
#pragma unroll
            for (int c = 0; c < 4; c++) acc[a][b][c] = 0.0f;

    constexpr int NCH = K1 / 64;
    load_chunk(0, 0);
    CP_COMMIT();
    for (int c = 0; c < NCH; c++) {
        if (c + 1 < NCH) { load_chunk(c + 1, (c + 1) & 1); CP_COMMIT(); CP_WAIT(1); }
        else             { CP_WAIT(0); }
        __syncthreads();
        uint32_t base = sb + (c & 1) * STG1;
#pragma unroll
        for (int ks = 0; ks < 4; ks++) {
            const uint32_t kx = (uint32_t)(ks * 32);
            uint32_t bh[2][4], bl[2][4];
#pragma unroll
            for (int j = 0; j < 2; j++) {
                ldm_x4(bh[j], base + 2 * ATSZ1 + (patB[j] ^ kx));
                ldm_x4(bl[j], base + 2 * ATSZ1 + BTSZ1 + (patB[j] ^ kx));
            }
#pragma unroll
            for (int am = 0; am < 2; am++) {
                uint32_t ah[4], al[4];
                ldm_x4(ah, base + (patA[am] ^ kx));
                ldm_x4(al, base + ATSZ1 + (patA[am] ^ kx));
#pragma unroll
                for (int nt = 0; nt < 4; nt++) {
                    const uint32_t* b_h = &bh[nt >> 1][(nt & 1) * 2];
                    const uint32_t* b_l = &bl[nt >> 1][(nt & 1) * 2];
                    mma_bf16(acc[am][nt], ah, b_h);
                    mma_bf16(acc[am][nt], ah, b_l);
                    mma_bf16(acc[am][nt], al, b_h);
                }
            }
        }
        __syncthreads();
    }

    const int gr = lane >> 2, gc = (lane & 3) * 2;
#pragma unroll
    for (int am = 0; am < 2; am++) {
#pragma unroll
        for (int nt = 0; nt < 4; nt++) {
            int n = n0 + wn * 32 + nt * 8 + gc;
#pragma unroll
            for (int h = 0; h < 2; h++) {
                int r = m0 + wm * 32 + am * 16 + gr + h * 8;
                uint32_t pk = ((uint32_t)fphi(acc[am][nt][h * 2 + 1]) << 16)
                            | fphi(acc[am][nt][h * 2 + 0]);
                *reinterpret_cast<uint32_t*>(g_P + (size_t)r * 512 + n) = pk;
            }
        }
    }
}

// ---- LAYER 2: out = relu(bn2(h1 @ W2^T)), fp16 1-term, BK=128 ----
// 256-B logical rows stored as even/odd 128-B subrows; subrow-parity step in
// the ldmatrix address is swz(o+128) = swz(o) ^ 0x90.
__global__ void __launch_bounds__(256, 2) gemm2_kernel(float* __restrict__ Cout) {
    extern __shared__ char dsm[];
    uint32_t sb = (smem_u32(dsm) + 1023) & ~1023u;
    const int tid = threadIdx.x, lane = tid & 31, wid = tid >> 5;
    const int wm = wid >> 2, wn = wid & 3;
    const int n0 = blockIdx.x * 128;
    const int m0 = blockIdx.y * BM;

    auto load_chunk = [&](int kc, int buf) {
        int k0 = kc * 128;
        uint32_t base = sb + buf * STG2;
#pragma unroll
        for (int i = tid; i < BM * 16; i += 256) {         // A: 64 x 256 B
            int r = i >> 4, c = i & 15;
            int sr = r * 2 + (c >> 3);
            uint32_t off = swz((uint32_t)(sr * 128 + (c & 7) * 16));
            cp_async16(base + off, g_h1 + (size_t)(m0 + r) * K2 + k0 + c * 8);
        }
#pragma unroll
        for (int i = tid; i < 128 * 16; i += 256) {        // B: 128 x 256 B
            int r = i >> 4, c = i & 15;
            int sr = r * 2 + (c >> 3);
            uint32_t off = swz((uint32_t)(sr * 128 + (c & 7) * 16));
            cp_async16(base + ATSZ2 + off, g_w2 + (size_t)(n0 + r) * K2 + k0 + c * 8);
        }
    };

    const int g8 = lane >> 3, i8 = lane & 7;
    uint32_t patA[2], patB[2];
#pragma unroll
    for (int am = 0; am < 2; am++) {
        int r = wm * 32 + am * 16 + (g8 & 1) * 8 + i8;
        patA[am] = swz((uint32_t)((r * 2) * 128 + (g8 >> 1) * 16));
    }
#pragma unroll
    for (int j = 0; j < 2; j++) {
        int r = wn * 32 + j * 16 + (g8 >> 1) * 8 + i8;
        patB[j] = swz((uint32_t)((r * 2) * 128 + (g8 & 1) * 16));
    }

    float acc[2][4][4];
#pragma unroll
    for (int a = 0; a < 2; a++)
#pragma unroll
        for (int b = 0; b < 4; b++)
#pragma unroll
            for (int c = 0; c < 4; c++) acc[a][b][c] = 0.0f;

    constexpr int NCH = K2 / 128;   // 4
    load_chunk(0, 0);
    CP_COMMIT();
    for (int c = 0; c < NCH; c++) {
        if (c + 1 < NCH) { load_chunk(c + 1, (c + 1) & 1); CP_COMMIT(); CP_WAIT(1); }
        else             { CP_WAIT(0); }
        __syncthreads();
        uint32_t base = sb + (c & 1) * STG2;
#pragma unroll
        for (int ks = 0; ks < 8; ks++) {
            const uint32_t kx = (uint32_t)(((ks & 3) * 32) ^ ((ks >> 2) * 0x90));
            uint32_t bh[2][4];
#pragma unroll
            for (int j = 0; j < 2; j++)
                ldm_x4(bh[j], base + ATSZ2 + (patB[j] ^ kx));
#pragma unroll
            for (int am = 0; am < 2; am++) {
                uint32_t ah[4];
                ldm_x4(ah, base + (patA[am] ^ kx));
#pragma unroll
                for (int nt = 0; nt < 4; nt++)
                    mma_fp16(acc[am][nt], ah, &bh[nt >> 1][(nt & 1) * 2]);
            }
        }
        __syncthreads();
    }

    const int gr = lane >> 2, gc = (lane & 3) * 2;
#pragma unroll
    for (int am = 0; am < 2; am++) {
#pragma unroll
        for (int nt = 0; nt < 4; nt++) {
            int n = n0 + wn * 32 + nt * 8 + gc;
            float s0 = g_s2[n], s1v = g_s2[n + 1];
            float t0 = g_t2[n], t1v = g_t2[n + 1];
#pragma unroll
            for (int h = 0; h < 2; h++) {
                int r = m0 + wm * 32 + am * 16 + gr + h * 8;
                float v0 = fmaxf(fmaf(acc[am][nt][h * 2 + 0], s0, t0), 0.0f);
                float v1 = fmaxf(fmaf(acc[am][nt][h * 2 + 1], s1v, t1v), 0.0f);
                *reinterpret_cast<float2*>(Cout + (size_t)r * 512 + n) = make_float2(v0, v1);
            }
        }
    }
}

// knn body: bit-exact branchless insertion (validated R12)
__device__ __forceinline__ void knn_body(int pblk, const float* __restrict__ xyz,
                                         const float* __restrict__ centers,
                                         char* dsm) {
    float4* sc = reinterpret_cast<float4*>(dsm);
    const int tid = threadIdx.x;
    int p = pblk * 256 + tid;
    int b = p >> 13;
    for (int g = tid; g < Gc; g += 256) {
        float cx = centers[(b * Gc + g) * 3 + 0];
        float cy = centers[(b * Gc + g) * 3 + 1];
        float cz = centers[(b * Gc + g) * 3 + 2];
        float cc = __fadd_rn(__fadd_rn(__fmul_rn(cx, cx), __fmul_rn(cy, cy)),
                             __fmul_rn(cz, cz));
        sc[g] = make_float4(cx, cy, cz, cc);
    }
    __syncthreads();

    float x = xyz[p * 3 + 0], y = xyz[p * 3 + 1], z = xyz[p * 3 + 2];
    float xx = __fadd_rn(__fadd_rn(__fmul_rn(x, x), __fmul_rn(y, y)),
                         __fmul_rn(z, z));
    float d0 = INFINITY, d1 = INFINITY, d2 = INFINITY;
    int   i0 = 0, i1 = 0, i2 = 0;
#pragma unroll 8
    for (int g = 0; g < Gc; g++) {
        float4 c = sc[g];
        float dot = __fmaf_rn(z, c.z, __fmaf_rn(y, c.y, __fmul_rn(x, c.x)));
        float d   = __fsub_rn(__fadd_rn(xx, c.w), __fmul_rn(2.0f, dot));
        bool c0 = d < d0, c1 = d < d1, c2 = d < d2;
        d2 = c1 ? d1 : (c2 ? d : d2);
        i2 = c1 ? i1 : (c2 ? g : i2);
        d1 = c0 ? d0 : (c1 ? d : d1);
        i1 = c0 ? i0 : (c1 ? g : i1);
        d0 = c0 ? d : d0;
        i0 = c0 ? g : i0;
    }
    float r0 = __fdiv_rn(1.0f, __fadd_rn(d0, 1e-8f));
    float r1 = __fdiv_rn(1.0f, __fadd_rn(d1, 1e-8f));
    float r2 = __fdiv_rn(1.0f, __fadd_rn(d2, 1e-8f));
    float rs = __fadd_rn(__fadd_rn(r0, r1), r2);
    g_idx[p * 3 + 0] = i0; g_idx[p * 3 + 1] = i1; g_idx[p * 3 + 2] = i2;
    g_wts[p * 3 + 0] = __fdiv_rn(r0, rs);
    g_wts[p * 3 + 1] = __fdiv_rn(r1, rs);
    g_wts[p * 3 + 2] = __fdiv_rn(r2, rs);
}

// Union: blocks [0,128) = gemm1, blocks [128,256) = knn
__global__ void __launch_bounds__(256, 2) gemm1_knn_kernel(
    const float* __restrict__ xyz, const float* __restrict__ centers) {
    extern __shared__ char dsm[];
    const int blk = blockIdx.x;
    if (blk < 128) {
        gemm1_body(blk & 3, blk >> 2, dsm);
    } else {
        knn_body(blk - 128, xyz, centers, dsm);
    }
}

// ---------------------------------------------------------------------------
// Blend: h1 = relu(bn1(blend(P_fp16))) -> single fp16
// ---------------------------------------------------------------------------
__global__ void blend_kernel() {
    int p = blockIdx.x * 2 + (threadIdx.x >> 7);
    int j = threadIdx.x & 127;
    int b = p >> 13;
    int r0 = b * Gc + g_idx[p * 3 + 0];
    int r1 = b * Gc + g_idx[p * 3 + 1];
    int r2 = b * Gc + g_idx[p * 3 + 2];
    float w0 = g_wts[p * 3 + 0], w1 = g_wts[p * 3 + 1], w2 = g_wts[p * 3 + 2];
    union { unsigned short u[4]; uint2 q; } A, C, E;
    A.q = *reinterpret_cast<const uint2*>(g_P + (size_t)r0 * 512 + j * 4);
    C.q = *reinterpret_cast<const uint2*>(g_P + (size_t)r1 * 512 + j * 4);
    E.q = *reinterpret_cast<const uint2*>(g_P + (size_t)r2 * 512 + j * 4);
    float4 s = reinterpret_cast<const float4*>(g_s1)[j];
    float4 t = reinterpret_cast<const float4*>(g_t1)[j];
    float sv[4] = {s.x, s.y, s.z, s.w};
    float tv[4] = {t.x, t.y, t.z, t.w};
    union { unsigned short u[4]; uint2 q; } Hq;
#pragma unroll
    for (int k = 0; k < 4; k++) {
        float blendv = w2 * fp2f(E.u[k]) + w1 * fp2f(C.u[k]) + w0 * fp2f(A.u[k]);
        float o = fmaxf(fmaf(blendv, sv[k], tv[k]), 0.0f);
        Hq.u[k] = fphi(o);
    }
    *reinterpret_cast<uint2*>(g_h1 + (size_t)p * 512 + j * 4) = Hq.q;
}

// ---------------------------------------------------------------------------
extern "C" void kernel_launch(void* const* d_in, const int* in_sizes, int n_in,
                              void* d_out, int out_size) {
    (void)in_sizes; (void)n_in; (void)out_size;
    const float* xyz     = (const float*)d_in[0];
    const float* centers = (const float*)d_in[1];
    const float* H4      = (const float*)d_in[2];
    const float* H8      = (const float*)d_in[3];
    const float* H12     = (const float*)d_in[4];
    const float* w1      = (const float*)d_in[5];
    const float* b1      = (const float*)d_in[6];
    const float* g1      = (const float*)d_in[7];
    const float* be1     = (const float*)d_in[8];
    const float* m1      = (const float*)d_in[9];
    const float* v1      = (const float*)d_in[10];
    const float* w2      = (const float*)d_in[11];
    const float* b2      = (const float*)d_in[12];
    const float* g2      = (const float*)d_in[13];
    const float* be2     = (const float*)d_in[14];
    const float* m2      = (const float*)d_in[15];
    const float* v2      = (const float*)d_in[16];
    float* out = (float*)d_out;

    cudaFuncSetAttribute(gemm1_knn_kernel, cudaFuncAttributeMaxDynamicSharedMemorySize, SMEM1);
    cudaFuncSetAttribute(gemm2_kernel, cudaFuncAttributeMaxDynamicSharedMemorySize, SMEM2);

    // 1) all preprocessing in one concurrent launch
    preproc_kernel<<<PRE_BLKS, 256>>>(
        (const float4*)H4, (const float4*)H8, (const float4*)H12,
        w1, w2, b1, g1, be1, m1, v1, b2, g2, be2, m2, v2);

    // 2) gemm1 (128 blocks) + knn (128 blocks) in one wave
    gemm1_knn_kernel<<<256, 256, SMEM1>>>(xyz, centers);

    // 3) blend + BN1 + ReLU -> h1 (single fp16)
    blend_kernel<<<Mtot / 2, 256>>>();

    // 4) out = relu(bn2(h1 @ W2^T)), fp16 single-term, BK=128
    gemm2_kernel<<<dim3(4, Mtot / 64), 256, SMEM2>>>(out);
}

// round 16
// speedup vs baseline: 1.8780x; 1.8780x over previous
#include <cuda_runtime.h>
#include <cuda_bf16.h>
#include <cuda_fp16.h>
#include <math.h>
#include <stdint.h>

#define Bc   4
#define Nc   8192
#define Gc   512
#define K1   1536
#define K2   512
#define Mtot (Bc * Nc)   // 32768
#define Mg   (Bc * Gc)   // 2048

// ---------------- scratch ----------------------------------------------------
__device__ unsigned short g_Fh[(size_t)Mg * K1];     // fused features hi (bf16)
__device__ unsigned short g_Fl[(size_t)Mg * K1];     // fused features lo
__device__ unsigned short g_P [(size_t)Mg * 512];    // F @ W1^T (fp16)
__device__ unsigned short g_h1 [(size_t)Mtot * K2];  // hidden (fp16, single)
__device__ unsigned short g_w1h[512 * K1], g_w1l[512 * K1];   // bf16 split
__device__ unsigned short g_w2 [512 * K2];                     // fp16 single
__device__ int   g_idx[Mtot * 3];
__device__ float g_wts[Mtot * 3];
__device__ float g_s1[512], g_t1[512], g_s2[512], g_t2[512];

// ---------------- helpers ----------------------------------------------------
__device__ __forceinline__ uint32_t smem_u32(const void* p) {
    uint32_t a;
    asm("{ .reg .u64 t; cvta.to.shared.u64 t, %1; cvt.u32.u64 %0, t; }" : "=r"(a) : "l"(p));
    return a;
}
__device__ __forceinline__ void cp_async16(uint32_t dst, const void* src) {
    asm volatile("cp.async.cg.shared.global [%0], [%1], 16;" :: "r"(dst), "l"(src));
}
#define CP_COMMIT() asm volatile("cp.async.commit_group;" ::: "memory")
#define CP_WAIT(n)  asm volatile("cp.async.wait_group %0;" :: "n"(n) : "memory")

__device__ __forceinline__ void ldm_x4(uint32_t* r, uint32_t a) {
    asm volatile("ldmatrix.sync.aligned.m8n8.x4.shared.b16 {%0,%1,%2,%3}, [%4];"
                 : "=r"(r[0]), "=r"(r[1]), "=r"(r[2]), "=r"(r[3]) : "r"(a));
}
__device__ __forceinline__ void mma_bf16(float* c, const uint32_t* a, const uint32_t* b) {
    asm volatile("mma.sync.aligned.m16n8k16.row.col.f32.bf16.bf16.f32 "
                 "{%0,%1,%2,%3}, {%4,%5,%6,%7}, {%8,%9}, {%0,%1,%2,%3};"
                 : "+f"(c[0]), "+f"(c[1]), "+f"(c[2]), "+f"(c[3])
                 : "r"(a[0]), "r"(a[1]), "r"(a[2]), "r"(a[3]), "r"(b[0]), "r"(b[1]));
}
__device__ __forceinline__ void mma_fp16(float* c, const uint32_t* a, const uint32_t* b) {
    asm volatile("mma.sync.aligned.m16n8k16.row.col.f32.f16.f16.f32 "
                 "{%0,%1,%2,%3}, {%4,%5,%6,%7}, {%8,%9}, {%0,%1,%2,%3};"
                 : "+f"(c[0]), "+f"(c[1]), "+f"(c[2]), "+f"(c[3])
                 : "r"(a[0]), "r"(a[1]), "r"(a[2]), "r"(a[3]), "r"(b[0]), "r"(b[1]));
}
__device__ __forceinline__ uint32_t swz(uint32_t o) { return o ^ ((o >> 3) & 0x70); }
__device__ __forceinline__ unsigned short bfhi(float v) {
    __nv_bfloat16 h = __float2bfloat16(v);
    return *(unsigned short*)&h;
}
__device__ __forceinline__ unsigned short bflo(float v, unsigned short hb) {
    __nv_bfloat16 h; *(unsigned short*)&h = hb;
    __nv_bfloat16 l = __float2bfloat16(v - __bfloat162float(h));
    return *(unsigned short*)&l;
}
__device__ __forceinline__ unsigned short fphi(float v) {
    __half h = __float2half_rn(v);
    return *(unsigned short*)&h;
}
__device__ __forceinline__ float fp2f(unsigned short u) {
    __half h; *(unsigned short*)&h = u;
    return __half2float(h);
}

// ---------------------------------------------------------------------------
// Union preprocess kernel (validated R11/R14)
// ---------------------------------------------------------------------------
#define PREP_BLKS  2
#define CONVW_BASE 2
#define CONVW_BLKS 3072
#define CONVF_BASE (CONVW_BASE + CONVW_BLKS)    // 3074
#define CONVF_BLKS 3072
#define PRE_BLKS   (CONVF_BASE + CONVF_BLKS)    // 6146

__global__ void __launch_bounds__(256) preproc_kernel(
    const float4* __restrict__ H4, const float4* __restrict__ H8,
    const float4* __restrict__ H12,
    const float* __restrict__ w1, const float* __restrict__ w2,
    const float* __restrict__ b1, const float* __restrict__ g1,
    const float* __restrict__ be1, const float* __restrict__ m1,
    const float* __restrict__ v1,
    const float* __restrict__ b2, const float* __restrict__ g2,
    const float* __restrict__ be2, const float* __restrict__ m2,
    const float* __restrict__ v2)
{
    const int blk = blockIdx.x, tid = threadIdx.x;
    if (blk < PREP_BLKS) {
        int i = blk * 256 + tid;
        if (i < 512) {
            float s = g1[i] * rsqrtf(v1[i] + 1e-5f);
            g_s1[i] = s;
            g_t1[i] = (b1[i] - m1[i]) * s + be1[i];
            float s2 = g2[i] * rsqrtf(v2[i] + 1e-5f);
            g_s2[i] = s2;
            g_t2[i] = (b2[i] - m2[i]) * s2 + be2[i];
        }
    } else if (blk < CONVF_BASE) {
        int i = (blk - CONVW_BASE) * 256 + tid;
        if (i < 512 * K1) {
            float v = w1[i];
            unsigned short h = bfhi(v);
            g_w1h[i] = h;
            g_w1l[i] = bflo(v, h);
        }
        if (i < 512 * K2) {
            g_w2[i] = fphi(w2[i]);
        }
    } else {
        int gid = (blk - CONVF_BASE) * 256 + tid;    // < Mg*384
        if (gid < Mg * 384) {
            int row = gid / 384;
            int c4  = gid - row * 384;
            int seg = c4 >> 7;
            int off = c4 & 127;
            const float4* H = (seg == 0) ? H4 : ((seg == 1) ? H8 : H12);
            float4 v = H[(size_t)row * 128 + off];
            float o[4] = {v.x, v.y, v.z, v.w};
            union { unsigned short u[4]; uint2 q; } Hq, Lq;
#pragma unroll
            for (int j = 0; j < 4; j++) {
                Hq.u[j] = bfhi(o[j]);
                Lq.u[j] = bflo(o[j], Hq.u[j]);
            }
            *reinterpret_cast<uint2*>(g_Fh + (size_t)gid * 4) = Hq.q;
            *reinterpret_cast<uint2*>(g_Fl + (size_t)gid * 4) = Lq.q;
        }
    }
}

// ---------------------------------------------------------------------------
// GEMM configs. BM=64, 2m x 4n warps, 2 CTAs/SM. All tiles 128-B rows (SW128,
// validated). gemm2 uses a 3-deep cp.async ring (24 KB/stage) to decouple
// load and compute across chunk boundaries.
// ---------------------------------------------------------------------------
static constexpr int BM    = 64;
static constexpr int ATSZ  = BM * 128;          // 8 KB
static constexpr int BTSZ  = 128 * 128;         // 16 KB
static constexpr int STG1  = 2 * ATSZ + 2 * BTSZ;   // 48 KB
static constexpr int SMEM1 = 2 * STG1 + 1024;
static constexpr int STG2  = ATSZ + BTSZ;       // 24 KB
static constexpr int SMEM2 = 3 * STG2 + 1024;   // 3-stage ring

// ---- LAYER 1 body: P = F @ W1^T, bf16 3-term split -> fp16 P (validated) ----
__device__ __forceinline__ void gemm1_body(int bx, int by, char* dsm) {
    uint32_t sb = (smem_u32(dsm) + 1023) & ~1023u;
    const int tid = threadIdx.x, lane = tid & 31, wid = tid >> 5;
    const int wm = wid >> 2, wn = wid & 3;
    const int n0 = bx * 128;
    const int m0 = by * BM;

    auto load_chunk = [&](int kc, int buf) {
        int k0 = kc * 64;
        uint32_t base = sb + buf * STG1;
#pragma unroll
        for (int i = tid; i < BM * 8; i += 256) {
            int r = i >> 3, c = i & 7;
            size_t go = (size_t)(m0 + r) * K1 + k0 + c * 8;
            uint32_t off = swz((uint32_t)(r * 128 + c * 16));
            cp_async16(base + off, g_Fh + go);
            cp_async16(base + ATSZ + off, g_Fl + go);
        }
#pragma unroll
        for (int i = tid; i < 128 * 8; i += 256) {
            int r = i >> 3, c = i & 7;
            size_t go = (size_t)(n0 + r) * K1 + k0 + c * 8;
            uint32_t off = swz((uint32_t)(r * 128 + c * 16));
            cp_async16(base + 2 * ATSZ + off, g_w1h + go);
            cp_async16(base + 2 * ATSZ + BTSZ + off, g_w1l + go);
        }
    };

    const int g8 = lane >> 3, i8 = lane & 7;
    uint32_t patA[2], patB[2];
#pragma unroll
    for (int am = 0; am < 2; am++) {
        int r = wm * 32 + am * 16 + (g8 & 1) * 8 + i8;
        patA[am] = swz((uint32_t)(r * 128 + (g8 >> 1) * 16));
    }
#pragma unroll
    for (int j = 0; j < 2; j++) {
        int r = wn * 32 + j * 16 + (g8 >> 1) * 8 + i8;
        patB[j] = swz((uint32_t)(r * 128 + (g8 & 1) * 16));
    }

    float acc[2][4][4];
#pragma unroll
    for (int a = 0; a < 2; a++)
#pragma unroll
        for (int b = 0; b < 4; b++)
#pragma unroll
            for (int c = 0; c < 4; c++) acc[a][b][c] = 0.0f;

    constexpr int NCH = K1 / 64;
    load_chunk(0, 0);
    CP_COMMIT();
    for (int c = 0; c < NCH; c++) {
        if (c + 1 < NCH) { load_chunk(c + 1, (c + 1) & 1); CP_COMMIT(); CP_WAIT(1); }
        else             { CP_WAIT(0); }
        __syncthreads();
        uint32_t base = sb + (c & 1) * STG1;
#pragma unroll
        for (int ks = 0; ks < 4; ks++) {
            const uint32_t kx = (uint32_t)(ks * 32);
            uint32_t bh[2][4], bl[2][4];
#pragma unroll
            for (int j = 0; j < 2; j++) {
                ldm_x4(bh[j], base + 2 * ATSZ + (patB[j] ^ kx));
                ldm_x4(bl[j], base + 2 * ATSZ + BTSZ + (patB[j] ^ kx));
            }
#pragma unroll
            for (int am = 0; am < 2; am++) {
                uint32_t ah[4], al[4];
                ldm_x4(ah, base + (patA[am] ^ kx));
                ldm_x4(al, base + ATSZ + (patA[am] ^ kx));
#pragma unroll
                for (int nt = 0; nt < 4; nt++) {
                    const uint32_t* b_h = &bh[nt >> 1][(nt & 1) * 2];
                    const uint32_t* b_l = &bl[nt >> 1][(nt & 1) * 2];
                    mma_bf16(acc[am][nt], ah, b_h);
                    mma_bf16(acc[am][nt], ah, b_l);
                    mma_bf16(acc[am][nt], al, b_h);
                }
            }
        }
        __syncthreads();
    }

    const int gr = lane >> 2, gc = (lane & 3) * 2;
#pragma unroll
    for (int am = 0; am < 2; am++) {
#pragma unroll
        for (int nt = 0; nt < 4; nt++) {
            int n = n0 + wn * 32 + nt * 8 + gc;
#pragma unroll
            for (int h = 0; h < 2; h++) {
                int r = m0 + wm * 32 + am * 16 + gr + h * 8;
                uint32_t pk = ((uint32_t)fphi(acc[am][nt][h * 2 + 1]) << 16)
                            | fphi(acc[am][nt][h * 2 + 0]);
                *reinterpret_cast<uint32_t*>(g_P + (size_t)r * 512 + n) = pk;
            }
        }
    }
}

// ---- LAYER 2: out = relu(bn2(h1 @ W2^T)), fp16 1-term, BK=64 (R14 layout),
//      3-stage cp.async ring ----
__global__ void __launch_bounds__(256, 2) gemm2_kernel(float* __restrict__ Cout) {
    extern __shared__ char dsm[];
    uint32_t sb = (smem_u32(dsm) + 1023) & ~1023u;
    const int tid = threadIdx.x, lane = tid & 31, wid = tid >> 5;
    const int wm = wid >> 2, wn = wid & 3;
    const int n0 = blockIdx.x * 128;
    const int m0 = blockIdx.y * BM;

    auto load_chunk = [&](int kc, int buf) {
        int k0 = kc * 64;
        uint32_t base = sb + buf * STG2;
#pragma unroll
        for (int i = tid; i < BM * 8; i += 256) {          // A: fp16 single
            int r = i >> 3, c = i & 7;
            size_t go = (size_t)(m0 + r) * K2 + k0 + c * 8;
            cp_async16(base + swz((uint32_t)(r * 128 + c * 16)), g_h1 + go);
        }
#pragma unroll
        for (int i = tid; i < 128 * 8; i += 256) {         // B: fp16 single
            int r = i >> 3, c = i & 7;
            size_t go = (size_t)(n0 + r) * K2 + k0 + c * 8;
            cp_async16(base + ATSZ + swz((uint32_t)(r * 128 + c * 16)), g_w2 + go);
        }
    };

    const int g8 = lane >> 3, i8 = lane & 7;
    uint32_t patA[2], patB[2];
#pragma unroll
    for (int am = 0; am < 2; am++) {
        int r = wm * 32 + am * 16 + (g8 & 1) * 8 + i8;
        patA[am] = swz((uint32_t)(r * 128 + (g8 >> 1) * 16));
    }
#pragma unroll
    for (int j = 0; j < 2; j++) {
        int r = wn * 32 + j * 16 + (g8 >> 1) * 8 + i8;
        patB[j] = swz((uint32_t)(r * 128 + (g8 & 1) * 16));
    }

    float acc[2][4][4];
#pragma unroll
    for (int a = 0; a < 2; a++)
#pragma unroll
        for (int b = 0; b < 4; b++)
#pragma unroll
            for (int c = 0; c < 4; c++) acc[a][b][c] = 0.0f;

    constexpr int NCH = K2 / 64;   // 8
    // 3-stage ring prologue: stages 0,1 in flight
    load_chunk(0, 0); CP_COMMIT();
    load_chunk(1, 1); CP_COMMIT();
    for (int c = 0; c < NCH; c++) {
        if (c + 2 < NCH) { load_chunk(c + 2, (c + 2) % 3); CP_COMMIT(); CP_WAIT(2); }
        else if (c + 1 < NCH) { CP_WAIT(1); }
        else                  { CP_WAIT(0); }
        __syncthreads();
        uint32_t base = sb + (c % 3) * STG2;
#pragma unroll
        for (int ks = 0; ks < 4; ks++) {
            const uint32_t kx = (uint32_t)(ks * 32);
            uint32_t bh[2][4];
#pragma unroll
            for (int j = 0; j < 2; j++)
                ldm_x4(bh[j], base + ATSZ + (patB[j] ^ kx));
#pragma unroll
            for (int am = 0; am < 2; am++) {
                uint32_t ah[4];
                ldm_x4(ah, base + (patA[am] ^ kx));
#pragma unroll
                for (int nt = 0; nt < 4; nt++)
                    mma_fp16(acc[am][nt], ah, &bh[nt >> 1][(nt & 1) * 2]);
            }
        }
        __syncthreads();
    }

    const int gr = lane >> 2, gc = (lane & 3) * 2;
#pragma unroll
    for (int am = 0; am < 2; am++) {
#pragma unroll
        for (int nt = 0; nt < 4; nt++) {
            int n = n0 + wn * 32 + nt * 8 + gc;
            float s0 = g_s2[n], s1v = g_s2[n + 1];
            float t0 = g_t2[n], t1v = g_t2[n + 1];
#pragma unroll
            for (int h = 0; h < 2; h++) {
                int r = m0 + wm * 32 + am * 16 + gr + h * 8;
                float v0 = fmaxf(fmaf(acc[am][nt][h * 2 + 0], s0, t0), 0.0f);
                float v1 = fmaxf(fmaf(acc[am][nt][h * 2 + 1], s1v, t1v), 0.0f);
                *reinterpret_cast<float2*>(Cout + (size_t)r * 512 + n) = make_float2(v0, v1);
            }
        }
    }
}

// knn body: bit-exact branchless insertion (validated R12)
__device__ __forceinline__ void knn_body(int pblk, const float* __restrict__ xyz,
                                         const float* __restrict__ centers,
                                         char* dsm) {
    float4* sc = reinterpret_cast<float4*>(dsm);
    const int tid = threadIdx.x;
    int p = pblk * 256 + tid;
    int b = p >> 13;
    for (int g = tid; g < Gc; g += 256) {
        float cx = centers[(b * Gc + g) * 3 + 0];
        float cy = centers[(b * Gc + g) * 3 + 1];
        float cz = centers[(b * Gc + g) * 3 + 2];
        float cc = __fadd_rn(__fadd_rn(__fmul_rn(cx, cx), __fmul_rn(cy, cy)),
                             __fmul_rn(cz, cz));
        sc[g] = make_float4(cx, cy, cz, cc);
    }
    __syncthreads();

    float x = xyz[p * 3 + 0], y = xyz[p * 3 + 1], z = xyz[p * 3 + 2];
    float xx = __fadd_rn(__fadd_rn(__fmul_rn(x, x), __fmul_rn(y, y)),
                         __fmul_rn(z, z));
    float d0 = INFINITY, d1 = INFINITY, d2 = INFINITY;
    int   i0 = 0, i1 = 0, i2 = 0;
#pragma unroll 8
    for (int g = 0; g < Gc; g++) {
        float4 c = sc[g];
        float dot = __fmaf_rn(z, c.z, __fmaf_rn(y, c.y, __fmul_rn(x, c.x)));
        float d   = __fsub_rn(__fadd_rn(xx, c.w), __fmul_rn(2.0f, dot));
        bool c0 = d < d0, c1 = d < d1, c2 = d < d2;
        d2 = c1 ? d1 : (c2 ? d : d2);
        i2 = c1 ? i1 : (c2 ? g : i2);
        d1 = c0 ? d0 : (c1 ? d : d1);
        i1 = c0 ? i0 : (c1 ? g : i1);
        d0 = c0 ? d : d0;
        i0 = c0 ? g : i0;
    }
    float r0 = __fdiv_rn(1.0f, __fadd_rn(d0, 1e-8f));
    float r1 = __fdiv_rn(1.0f, __fadd_rn(d1, 1e-8f));
    float r2 = __fdiv_rn(1.0f, __fadd_rn(d2, 1e-8f));
    float rs = __fadd_rn(__fadd_rn(r0, r1), r2);
    g_idx[p * 3 + 0] = i0; g_idx[p * 3 + 1] = i1; g_idx[p * 3 + 2] = i2;
    g_wts[p * 3 + 0] = __fdiv_rn(r0, rs);
    g_wts[p * 3 + 1] = __fdiv_rn(r1, rs);
    g_wts[p * 3 + 2] = __fdiv_rn(r2, rs);
}

// Union: blocks [0,128) = gemm1, blocks [128,256) = knn
__global__ void __launch_bounds__(256, 2) gemm1_knn_kernel(
    const float* __restrict__ xyz, const float* __restrict__ centers) {
    extern __shared__ char dsm[];
    const int blk = blockIdx.x;
    if (blk < 128) {
        gemm1_body(blk & 3, blk >> 2, dsm);
    } else {
        knn_body(blk - 128, xyz, centers, dsm);
    }
}

// ---------------------------------------------------------------------------
// Blend: h1 = relu(bn1(blend(P_fp16))) -> single fp16 (numerics validated R15)
// ---------------------------------------------------------------------------
__global__ void blend_kernel() {
    int p = blockIdx.x * 2 + (threadIdx.x >> 7);
    int j = threadIdx.x & 127;
    int b = p >> 13;
    int r0 = b * Gc + g_idx[p * 3 + 0];
    int r1 = b * Gc + g_idx[p * 3 + 1];
    int r2 = b * Gc + g_idx[p * 3 + 2];
    float w0 = g_wts[p * 3 + 0], w1 = g_wts[p * 3 + 1], w2 = g_wts[p * 3 + 2];
    union { unsigned short u[4]; uint2 q; } A, C, E;
    A.q = *reinterpret_cast<const uint2*>(g_P + (size_t)r0 * 512 + j * 4);
    C.q = *reinterpret_cast<const uint2*>(g_P + (size_t)r1 * 512 + j * 4);
    E.q = *reinterpret_cast<const uint2*>(g_P + (size_t)r2 * 512 + j * 4);
    float4 s = reinterpret_cast<const float4*>(g_s1)[j];
    float4 t = reinterpret_cast<const float4*>(g_t1)[j];
    float sv[4] = {s.x, s.y, s.z, s.w};
    float tv[4] = {t.x, t.y, t.z, t.w};
    union { unsigned short u[4]; uint2 q; } Hq;
#pragma unroll
    for (int k = 0; k < 4; k++) {
        float blendv = w2 * fp2f(E.u[k]) + w1 * fp2f(C.u[k]) + w0 * fp2f(A.u[k]);
        float o = fmaxf(fmaf(blendv, sv[k], tv[k]), 0.0f);
        Hq.u[k] = fphi(o);
    }
    *reinterpret_cast<uint2*>(g_h1 + (size_t)p * 512 + j * 4) = Hq.q;
}

// ---------------------------------------------------------------------------
extern "C" void kernel_launch(void* const* d_in, const int* in_sizes, int n_in,
                              void* d_out, int out_size) {
    (void)in_sizes; (void)n_in; (void)out_size;
    const float* xyz     = (const float*)d_in[0];
    const float* centers = (const float*)d_in[1];
    const float* H4      = (const float*)d_in[2];
    const float* H8      = (const float*)d_in[3];
    const float* H12     = (const float*)d_in[4];
    const float* w1      = (const float*)d_in[5];
    const float* b1      = (const float*)d_in[6];
    const float* g1      = (const float*)d_in[7];
    const float* be1     = (const float*)d_in[8];
    const float* m1      = (const float*)d_in[9];
    const float* v1      = (const float*)d_in[10];
    const float* w2      = (const float*)d_in[11];
    const float* b2      = (const float*)d_in[12];
    const float* g2      = (const float*)d_in[13];
    const float* be2     = (const float*)d_in[14];
    const float* m2      = (const float*)d_in[15];
    const float* v2      = (const float*)d_in[16];
    float* out = (float*)d_out;

    cudaFuncSetAttribute(gemm1_knn_kernel, cudaFuncAttributeMaxDynamicSharedMemorySize, SMEM1);
    cudaFuncSetAttribute(gemm2_kernel, cudaFuncAttributeMaxDynamicSharedMemorySize, SMEM2);

    // 1) all preprocessing in one concurrent launch
    preproc_kernel<<<PRE_BLKS, 256>>>(
        (const float4*)H4, (const float4*)H8, (const float4*)H12,
        w1, w2, b1, g1, be1, m1, v1, b2, g2, be2, m2, v2);

    // 2) gemm1 (128 blocks) + knn (128 blocks) in one wave
    gemm1_knn_kernel<<<256, 256, SMEM1>>>(xyz, centers);

    // 3) blend + BN1 + ReLU -> h1 (single fp16)
    blend_kernel<<<Mtot / 2, 256>>>();

    // 4) out = relu(bn2(h1 @ W2^T)), fp16 single-term, BK=64, 3-stage ring
    gemm2_kernel<<<dim3(4, Mtot / 64), 256, SMEM2>>>(out);
}